// round 2
// baseline (speedup 1.0000x reference)
#include <cuda_runtime.h>

#define HH 96
#define WW 96
#define HW 9216
#define NE 64
#define ND 128
#define NK 4
#define NB 2

// -------- scratch (no allocations allowed) --------
__device__ float g_queries[NB * NE * HW];
__device__ float g_keys[NK * NB * NE * HW];
__device__ float g_values[NB * NE * HW];

__device__ __forceinline__ float fast_tanh(float x) {
    // tanh(x) = 1 - 2/(e^{2x}+1); safe at +/-inf, ~1e-6 rel err
    float e = __expf(2.0f * x);
    return 1.0f - __fdividef(2.0f, e + 1.0f);
}

// ============================================================
// 1x1 conv:  out[img][o][p] = sum_ci w[o][ci] * x[img][ci][p] + b[o]
// block: 64 out channels x 128 pixels. 256 threads, 8ch x 4px per thread.
// ============================================================
template <int CIN>
__global__ void __launch_bounds__(256) conv1x1_kernel(
    const float* __restrict__ x, const float* __restrict__ w,
    const float* __restrict__ bias, float* __restrict__ out)
{
    __shared__ __align__(16) float xs[16][128];
    __shared__ __align__(16) float ws[16][64];
    int tid = threadIdx.x;
    int lane = tid & 31, cg = tid >> 5;
    int img = blockIdx.y;
    int p0 = blockIdx.x * 128;
    const float* xb = x + (size_t)img * CIN * HW + p0;

    float acc[8][4];
#pragma unroll
    for (int e = 0; e < 8; e++)
#pragma unroll
        for (int j = 0; j < 4; j++) acc[e][j] = 0.f;

    for (int c0 = 0; c0 < CIN; c0 += 16) {
#pragma unroll
        for (int rep = 0; rep < 2; rep++) {
            int lin = tid + rep * 256;
            int ci = lin >> 5, px = (lin & 31) * 4;
            *(float4*)&xs[ci][px] = *(const float4*)&xb[(size_t)(c0 + ci) * HW + px];
        }
        {
            int ci = tid >> 4, o4 = (tid & 15) * 4;
#pragma unroll
            for (int t = 0; t < 4; t++)
                ws[ci][o4 + t] = w[(o4 + t) * CIN + c0 + ci];
        }
        __syncthreads();
#pragma unroll
        for (int ci = 0; ci < 16; ci++) {
            float4 xv = *(float4*)&xs[ci][lane * 4];
            float4 wa = *(float4*)&ws[ci][cg * 8];
            float4 wb = *(float4*)&ws[ci][cg * 8 + 4];
            float xvv[4] = {xv.x, xv.y, xv.z, xv.w};
            float wv[8] = {wa.x, wa.y, wa.z, wa.w, wb.x, wb.y, wb.z, wb.w};
#pragma unroll
            for (int e = 0; e < 8; e++)
#pragma unroll
                for (int j = 0; j < 4; j++)
                    acc[e][j] = fmaf(wv[e], xvv[j], acc[e][j]);
        }
        __syncthreads();
    }
    float* ob = out + (size_t)img * NE * HW + p0;
#pragma unroll
    for (int e = 0; e < 8; e++) {
        int o = cg * 8 + e;
        float bb = bias[o];
        float4 r = make_float4(acc[e][0] + bb, acc[e][1] + bb,
                               acc[e][2] + bb, acc[e][3] + bb);
        *(float4*)&ob[(size_t)o * HW + lane * 4] = r;
    }
}

// ============================================================
// 3x3 conv (SAME, cross-correlation): 128 -> 64 channels.
// 8x8 pixel tiles, grid (12,12,B) = 288 blocks. 256 threads:
// cg=tid>>5 -> 8 channels; lane -> (prow=lane>>2, pcol0=(lane&3)*2) -> 2 px.
// ============================================================
__global__ void __launch_bounds__(256) conv3x3_kernel(
    const float* __restrict__ x,    // [B][128][H][W]
    const float* __restrict__ wv,   // [64][128][3][3]
    const float* __restrict__ bias, // [64]
    float* __restrict__ out)        // [B][64][H][W]
{
    __shared__ __align__(16) float xs[16][110];     // [ci][hr*11+hc], 10x10 halo
    __shared__ __align__(16) float ws[16][9][64];   // repacked [ci][tap][o]
    int tid = threadIdx.x;
    int lane = tid & 31, cg = tid >> 5;
    int b = blockIdx.z;
    int yo = blockIdx.y * 8, xo = blockIdx.x * 8;
    int prow = lane >> 2, pcol0 = (lane & 3) * 2;
    const float* xb = x + (size_t)b * ND * HW;

    float acc[8][2];
#pragma unroll
    for (int e = 0; e < 8; e++) { acc[e][0] = 0.f; acc[e][1] = 0.f; }

    for (int c0 = 0; c0 < ND; c0 += 16) {
        for (int lin = tid; lin < 1600; lin += 256) {
            int hc = lin % 10; int t = lin / 10; int hr = t % 10; int ci = t / 10;
            int gy = yo - 1 + hr, gx = xo - 1 + hc;
            float v = 0.f;
            if ((unsigned)gy < HH && (unsigned)gx < WW)
                v = xb[(size_t)(c0 + ci) * HW + gy * WW + gx];
            xs[ci][hr * 11 + hc] = v;
        }
        for (int lin = tid; lin < 9216; lin += 256) {
            int o = lin & 63; int t = lin >> 6; int tap = t % 9; int ci = t / 9;
            ws[ci][tap][o] = wv[(size_t)o * (ND * 9) + (c0 + ci) * 9 + tap];
        }
        __syncthreads();
#pragma unroll
        for (int ci = 0; ci < 16; ci++) {
#pragma unroll
            for (int dr = 0; dr < 3; dr++) {
                float xr[4];
#pragma unroll
                for (int i = 0; i < 4; i++)
                    xr[i] = xs[ci][(prow + dr) * 11 + pcol0 + i];
#pragma unroll
                for (int dc = 0; dc < 3; dc++) {
                    float4 wa = *(float4*)&ws[ci][dr * 3 + dc][cg * 8];
                    float4 wb = *(float4*)&ws[ci][dr * 3 + dc][cg * 8 + 4];
                    float wr[8] = {wa.x, wa.y, wa.z, wa.w, wb.x, wb.y, wb.z, wb.w};
#pragma unroll
                    for (int e = 0; e < 8; e++) {
                        acc[e][0] = fmaf(wr[e], xr[dc], acc[e][0]);
                        acc[e][1] = fmaf(wr[e], xr[dc + 1], acc[e][1]);
                    }
                }
            }
        }
        __syncthreads();
    }
    float* ob = out + (size_t)b * NE * HW;
#pragma unroll
    for (int e = 0; e < 8; e++) {
        int o = cg * 8 + e;
        float bb = bias[o];
        float2 r = make_float2(acc[e][0] + bb, acc[e][1] + bb);
        *(float2*)&ob[(size_t)o * HW + (yo + prow) * WW + xo + pcol0] = r;
    }
}

// ============================================================
// Fused attention + output projection.
// 8x8 pixel tile per block, 8 warps, warp = tile row; lanes over E.
// ============================================================
__device__ __forceinline__ void final_accum(
    const float* __restrict__ cat, const float* __restrict__ wsl,
    int lane, int wr, float out0[8], float out1[8])
{
#pragma unroll
    for (int it = 0; it < 8; it++) {
        int i0 = it * 8;
        float w0[8], w1[8];
#pragma unroll
        for (int jj = 0; jj < 8; jj++) {
            w0[jj] = wsl[(i0 + jj) * 65 + lane];
            w1[jj] = wsl[(i0 + jj) * 65 + 32 + lane];
        }
#pragma unroll
        for (int j = 0; j < 8; j++) {
            const float* cp = &cat[(wr * 8 + j) * 68 + i0];
            float4 ca = *(const float4*)cp;
            float4 cb = *(const float4*)(cp + 4);
            float s0 = out0[j];
            s0 = fmaf(w0[0], ca.x, s0); s0 = fmaf(w0[1], ca.y, s0);
            s0 = fmaf(w0[2], ca.z, s0); s0 = fmaf(w0[3], ca.w, s0);
            s0 = fmaf(w0[4], cb.x, s0); s0 = fmaf(w0[5], cb.y, s0);
            s0 = fmaf(w0[6], cb.z, s0); s0 = fmaf(w0[7], cb.w, s0);
            out0[j] = s0;
            float s1 = out1[j];
            s1 = fmaf(w1[0], ca.x, s1); s1 = fmaf(w1[1], ca.y, s1);
            s1 = fmaf(w1[2], ca.z, s1); s1 = fmaf(w1[3], ca.w, s1);
            s1 = fmaf(w1[4], cb.x, s1); s1 = fmaf(w1[5], cb.y, s1);
            s1 = fmaf(w1[6], cb.z, s1); s1 = fmaf(w1[7], cb.w, s1);
            out1[j] = s1;
        }
    }
}

__global__ void __launch_bounds__(256) attn_kernel(
    const float* __restrict__ contexts,  // [K][B][E][H][W]
    const float* __restrict__ w_agg,     // [64]
    const float* __restrict__ b_agg_p,   // [1]
    const float* __restrict__ w_attn,    // [64][320]
    const float* __restrict__ b_attn,    // [64]
    float* __restrict__ out)             // [B][64][H][W]
{
    extern __shared__ __align__(16) float sm[];
    float* qs  = sm;                  // [64 pix][68]
    float* ks  = qs + 64 * 68;        // [100 halo pix][68]
    float* cs  = ks + 100 * 68;       // [100 halo pix][68]
    float* cat = cs + 100 * 68;       // [64 pix][68]
    float* wsl = cat + 64 * 68;       // [64 i][65] (w_attn slice, [i][o])

    int tid = threadIdx.x, lane = tid & 31, wr = tid >> 5;
    int b = blockIdx.z, yo = blockIdx.y * 8, xo = blockIdx.x * 8;

    float wagg0 = w_agg[lane], wagg1 = w_agg[lane + 32];
    float bagg = b_agg_p[0];

    // load queries tile + values tile (-> cat) + w_attn slice 0
    for (int lin = tid; lin < 4096; lin += 256) {
        int col = lin & 7, row = (lin >> 3) & 7, e = lin >> 6;
        int g = (b * NE + e) * HW + (yo + row) * WW + xo + col;
        qs[(row * 8 + col) * 68 + e] = g_queries[g];
        cat[(row * 8 + col) * 68 + e] = g_values[g];
    }
    for (int lin = tid; lin < 4096; lin += 256) {
        int i = lin & 63, o = lin >> 6;
        wsl[i * 65 + o] = w_attn[o * 320 + i];
    }
    __syncthreads();

    float out0[8], out1[8];
#pragma unroll
    for (int j = 0; j < 8; j++) { out0[j] = 0.f; out1[j] = 0.f; }
    final_accum(cat, wsl, lane, wr, out0, out1);

    for (int k = 0; k < NK; k++) {
        __syncthreads();
        const float* kb = g_keys + (size_t)(k * NB + b) * NE * HW;
        const float* cb = contexts + (size_t)(k * NB + b) * NE * HW;
        for (int lin = tid; lin < 6400; lin += 256) {
            int hc = lin % 10; int t = lin / 10; int hr = t % 10; int e = t / 10;
            int gy = yo - 1 + hr, gx = xo - 1 + hc;
            float kv = 0.f, cv = 0.f;
            if ((unsigned)gy < HH && (unsigned)gx < WW) {
                int g = e * HW + gy * WW + gx;
                kv = kb[g]; cv = cb[g];
            }
            ks[(hr * 10 + hc) * 68 + e] = kv;
            cs[(hr * 10 + hc) * 68 + e] = cv;
        }
        for (int lin = tid; lin < 4096; lin += 256) {
            int i = lin & 63, o = lin >> 6;
            wsl[i * 65 + o] = w_attn[o * 320 + (k + 1) * 64 + i];
        }
        __syncthreads();

        for (int j = 0; j < 8; j++) {
            int pix = wr * 8 + j;
            float q0 = qs[pix * 68 + lane];
            float q1 = qs[pix * 68 + 32 + lane];
            float sc[9];
#pragma unroll
            for (int n = 0; n < 9; n++) {
                int dr = n / 3, dc = n % 3;
                int hp = (wr + dr) * 10 + (j + dc);
                float t0 = fast_tanh(q0 + ks[hp * 68 + lane]);
                float t1 = fast_tanh(q1 + ks[hp * 68 + 32 + lane]);
                float part = fmaf(wagg0, t0, wagg1 * t1);
#pragma unroll
                for (int off = 16; off; off >>= 1)
                    part += __shfl_xor_sync(0xffffffffu, part, off);
                bool valid = ((unsigned)(yo + wr + dr - 1) < HH) &&
                             ((unsigned)(xo + j + dc - 1) < WW);
                sc[n] = valid ? (part + bagg) : -1e30f;
            }
            float m = sc[0];
#pragma unroll
            for (int n = 1; n < 9; n++) m = fmaxf(m, sc[n]);
            float p[9], ps = 0.f;
#pragma unroll
            for (int n = 0; n < 9; n++) { p[n] = __expf(sc[n] - m); ps += p[n]; }
            float rinv = 1.0f / ps;
            float a0 = 0.f, a1 = 0.f;
#pragma unroll
            for (int n = 0; n < 9; n++) {
                int hp = (wr + n / 3) * 10 + (j + n % 3);
                a0 = fmaf(p[n], cs[hp * 68 + lane], a0);
                a1 = fmaf(p[n], cs[hp * 68 + 32 + lane], a1);
            }
            cat[pix * 68 + lane] = a0 * rinv;
            cat[pix * 68 + 32 + lane] = a1 * rinv;
        }
        __syncwarp();
        final_accum(cat, wsl, lane, wr, out0, out1);
    }

    // epilogue: bias + LeakyReLU(0.2), transpose through smem, coalesced store
    float ba0 = b_attn[lane], ba1 = b_attn[lane + 32];
    __syncthreads();
#pragma unroll
    for (int j = 0; j < 8; j++) {
        int pix = wr * 8 + j;
        float r0 = out0[j] + ba0; r0 = (r0 >= 0.f) ? r0 : 0.2f * r0;
        float r1 = out1[j] + ba1; r1 = (r1 >= 0.f) ? r1 : 0.2f * r1;
        cat[pix * 68 + lane] = r0;
        cat[pix * 68 + 32 + lane] = r1;
    }
    __syncthreads();
    for (int lin = tid; lin < 4096; lin += 256) {
        int col = lin & 7, row = (lin >> 3) & 7, e = lin >> 6;
        out[(b * NE + e) * HW + (yo + row) * WW + xo + col] =
            cat[(row * 8 + col) * 68 + e];
    }
}

// ============================================================
extern "C" void kernel_launch(void* const* d_in, const int* in_sizes, int n_in,
                              void* d_out, int out_size)
{
    (void)in_sizes; (void)n_in; (void)out_size;
    const float* contexts = (const float*)d_in[0];
    const float* decoded  = (const float*)d_in[1];
    const float* w_enc    = (const float*)d_in[2];
    const float* b_enc    = (const float*)d_in[3];
    const float* w_dec    = (const float*)d_in[4];
    const float* b_dec    = (const float*)d_in[5];
    const float* w_agg    = (const float*)d_in[6];
    const float* b_agg    = (const float*)d_in[7];
    const float* w_val    = (const float*)d_in[8];
    const float* b_val    = (const float*)d_in[9];
    const float* w_attn   = (const float*)d_in[10];
    const float* b_attn   = (const float*)d_in[11];
    float* out = (float*)d_out;

    float *gq, *gk, *gv;
    cudaGetSymbolAddress((void**)&gq, g_queries);
    cudaGetSymbolAddress((void**)&gk, g_keys);
    cudaGetSymbolAddress((void**)&gv, g_values);

    conv1x1_kernel<ND><<<dim3(72, NB), 256>>>(decoded, w_dec, b_dec, gq);
    conv1x1_kernel<NE><<<dim3(72, NK * NB), 256>>>(contexts, w_enc, b_enc, gk);
    conv3x3_kernel<<<dim3(12, 12, NB), 256>>>(decoded, w_val, b_val, gv);

    const int SMEM_ATTN = (64 * 68 + 100 * 68 + 100 * 68 + 64 * 68 + 64 * 65) * 4;
    cudaFuncSetAttribute(attn_kernel,
                         cudaFuncAttributeMaxDynamicSharedMemorySize, SMEM_ATTN);
    attn_kernel<<<dim3(12, 12, NB), 256, SMEM_ATTN>>>(
        contexts, w_agg, b_agg, w_attn, b_attn, out);
}

// round 3
// speedup vs baseline: 1.5335x; 1.5335x over previous
#include <cuda_runtime.h>

#define HH 96
#define WW 96
#define HW 9216
#define NE 64
#define ND 128
#define NK 4
#define NB 2

typedef unsigned long long ull;

__device__ float g_queries[NB * NE * HW];
__device__ float g_keys[NK * NB * NE * HW];
__device__ float g_values[NB * NE * HW];
__device__ float g_wpack[ND * 9 * NE];   // [ci][tap][o]
__device__ float g_wdecT[ND * NE];       // [ci][o]
__device__ float g_wencT[NE * NE];       // [ci][o]
__device__ float g_wattnT[5 * NE * NE];  // [i][o]

__device__ __forceinline__ ull fma2(ull a, ull b, ull c) {
    ull d;
    asm("fma.rn.f32x2 %0, %1, %2, %3;" : "=l"(d) : "l"(a), "l"(b), "l"(c));
    return d;
}
__device__ __forceinline__ ull pack2(float x, float y) {
    ull r; asm("mov.b64 %0, {%1, %2};" : "=l"(r) : "f"(x), "f"(y)); return r;
}
__device__ __forceinline__ float2 unpack2(ull v) {
    float lo, hi; asm("mov.b64 {%0, %1}, %2;" : "=f"(lo), "=f"(hi) : "l"(v));
    return make_float2(lo, hi);
}
__device__ __forceinline__ float tanh_fast(float x) {
    float y; asm("tanh.approx.f32 %0, %1;" : "=f"(y) : "f"(x)); return y;
}

// ============================================================
__global__ void __launch_bounds__(256) repack_kernel(
    const float* __restrict__ wv, const float* __restrict__ wd,
    const float* __restrict__ we, const float* __restrict__ wa)
{
    int i = blockIdx.x * 256 + threadIdx.x;
    if (i < 73728) {
        int o = i & 63; int t = i >> 6; int tap = t % 9; int ci = t / 9;
        g_wpack[i] = wv[(size_t)o * (ND * 9) + ci * 9 + tap];
    } else if (i < 81920) {
        int r = i - 73728; int o = r & 63; int ci = r >> 6;
        g_wdecT[r] = wd[o * ND + ci];
    } else if (i < 86016) {
        int r = i - 81920; int o = r & 63; int ci = r >> 6;
        g_wencT[r] = we[o * NE + ci];
    } else if (i < 106496) {
        int r = i - 86016; int o = r & 63; int ii = r >> 6;
        g_wattnT[r] = wa[o * 320 + ii];
    }
}

// ============================================================
// keys 1x1 conv, f32x2 over e-pairs. 64 out ch x 128 px per block.
// ============================================================
__global__ void __launch_bounds__(256) keys_kernel(
    const float* __restrict__ x, const float* __restrict__ bias,
    float* __restrict__ out)
{
    __shared__ __align__(16) float xs[16][128];
    __shared__ __align__(16) float ws[16 * 64];
    int tid = threadIdx.x, lane = tid & 31, cg = tid >> 5;
    int img = blockIdx.y;
    int p0 = blockIdx.x * 128;
    const float* xb = x + (size_t)img * NE * HW + p0;

    ull acc2[4][4];
#pragma unroll
    for (int ep = 0; ep < 4; ep++)
#pragma unroll
        for (int px = 0; px < 4; px++) acc2[ep][px] = 0ull;

    for (int c0 = 0; c0 < NE; c0 += 16) {
#pragma unroll
        for (int rep = 0; rep < 2; rep++) {
            int lin = tid + rep * 256;
            int ci = lin >> 5, px4 = (lin & 31) * 4;
            *(float4*)&xs[ci][px4] = *(const float4*)&xb[(size_t)(c0 + ci) * HW + px4];
        }
        ((float4*)ws)[tid] = ((const float4*)(g_wencT + c0 * 64))[tid];
        __syncthreads();
#pragma unroll
        for (int ci = 0; ci < 16; ci++) {
            float4 xv = *(float4*)&xs[ci][lane * 4];
            ull sx[4] = {pack2(xv.x, xv.x), pack2(xv.y, xv.y),
                         pack2(xv.z, xv.z), pack2(xv.w, xv.w)};
            ulonglong2 wa = *(const ulonglong2*)&ws[ci * 64 + cg * 8];
            ulonglong2 wb = *(const ulonglong2*)&ws[ci * 64 + cg * 8 + 4];
#pragma unroll
            for (int px = 0; px < 4; px++) {
                acc2[0][px] = fma2(wa.x, sx[px], acc2[0][px]);
                acc2[1][px] = fma2(wa.y, sx[px], acc2[1][px]);
                acc2[2][px] = fma2(wb.x, sx[px], acc2[2][px]);
                acc2[3][px] = fma2(wb.y, sx[px], acc2[3][px]);
            }
        }
        __syncthreads();
    }
    float* ob = out + (size_t)img * NE * HW + p0;
#pragma unroll
    for (int ep = 0; ep < 4; ep++) {
        float2 v0 = unpack2(acc2[ep][0]), v1 = unpack2(acc2[ep][1]);
        float2 v2 = unpack2(acc2[ep][2]), v3 = unpack2(acc2[ep][3]);
        int o0 = cg * 8 + ep * 2;
        float b0 = bias[o0], b1 = bias[o0 + 1];
        *(float4*)&ob[(size_t)o0 * HW + lane * 4] =
            make_float4(v0.x + b0, v1.x + b0, v2.x + b0, v3.x + b0);
        *(float4*)&ob[(size_t)(o0 + 1) * HW + lane * 4] =
            make_float4(v0.y + b1, v1.y + b1, v2.y + b1, v3.y + b1);
    }
}

// ============================================================
// 3x3 conv (values) + fused queries 1x1, f32x2 over e-pairs.
// 8x8 px tiles; thread: 4 e-pairs x 2 px.
// ============================================================
__global__ void __launch_bounds__(256, 2) conv3x3q_kernel(
    const float* __restrict__ x, const float* __restrict__ bias_v,
    const float* __restrict__ bias_q,
    float* __restrict__ outv, float* __restrict__ outq)
{
    __shared__ __align__(16) float xs[16][112];
    __shared__ __align__(16) float ws[16 * 9 * 64];
    __shared__ __align__(16) float wq[16 * 64];
    int tid = threadIdx.x, lane = tid & 31, cg = tid >> 5;
    int b = blockIdx.z;
    int yo = blockIdx.y * 8, xo = blockIdx.x * 8;
    int prow = lane >> 2, pcol0 = (lane & 3) * 2;
    const float* xb = x + (size_t)b * ND * HW;

    ull accv[4][2], accq[4][2];
#pragma unroll
    for (int ep = 0; ep < 4; ep++) {
        accv[ep][0] = accv[ep][1] = 0ull;
        accq[ep][0] = accq[ep][1] = 0ull;
    }

    for (int c0 = 0; c0 < ND; c0 += 16) {
        for (int lin = tid; lin < 1600; lin += 256) {
            int hc = lin % 10; int t = lin / 10; int hr = t % 10; int ci = t / 10;
            int gy = yo - 1 + hr, gx = xo - 1 + hc;
            float v = 0.f;
            if ((unsigned)gy < HH && (unsigned)gx < WW)
                v = xb[(size_t)(c0 + ci) * HW + gy * WW + gx];
            xs[ci][hr * 11 + hc] = v;
        }
#pragma unroll
        for (int r = 0; r < 9; r++)
            ((float4*)ws)[tid + r * 256] =
                ((const float4*)(g_wpack + c0 * 576))[tid + r * 256];
        ((float4*)wq)[tid] = ((const float4*)(g_wdecT + c0 * 64))[tid];
        __syncthreads();
#pragma unroll
        for (int ci = 0; ci < 16; ci++) {
#pragma unroll
            for (int dr = 0; dr < 3; dr++) {
                int rb = (prow + dr) * 11 + pcol0;
                float x0 = xs[ci][rb], x1 = xs[ci][rb + 1];
                float x2 = xs[ci][rb + 2], x3 = xs[ci][rb + 3];
                ull sx[4] = {pack2(x0, x0), pack2(x1, x1),
                             pack2(x2, x2), pack2(x3, x3)};
#pragma unroll
                for (int dc = 0; dc < 3; dc++) {
                    const float* wp = ws + (ci * 9 + dr * 3 + dc) * 64 + cg * 8;
                    ulonglong2 wa = *(const ulonglong2*)wp;
                    ulonglong2 wb = *(const ulonglong2*)(wp + 4);
                    accv[0][0] = fma2(wa.x, sx[dc], accv[0][0]);
                    accv[0][1] = fma2(wa.x, sx[dc + 1], accv[0][1]);
                    accv[1][0] = fma2(wa.y, sx[dc], accv[1][0]);
                    accv[1][1] = fma2(wa.y, sx[dc + 1], accv[1][1]);
                    accv[2][0] = fma2(wb.x, sx[dc], accv[2][0]);
                    accv[2][1] = fma2(wb.x, sx[dc + 1], accv[2][1]);
                    accv[3][0] = fma2(wb.y, sx[dc], accv[3][0]);
                    accv[3][1] = fma2(wb.y, sx[dc + 1], accv[3][1]);
                }
                if (dr == 1) {
                    const float* qp = wq + ci * 64 + cg * 8;
                    ulonglong2 qa = *(const ulonglong2*)qp;
                    ulonglong2 qb = *(const ulonglong2*)(qp + 4);
                    accq[0][0] = fma2(qa.x, sx[1], accq[0][0]);
                    accq[0][1] = fma2(qa.x, sx[2], accq[0][1]);
                    accq[1][0] = fma2(qa.y, sx[1], accq[1][0]);
                    accq[1][1] = fma2(qa.y, sx[2], accq[1][1]);
                    accq[2][0] = fma2(qb.x, sx[1], accq[2][0]);
                    accq[2][1] = fma2(qb.x, sx[2], accq[2][1]);
                    accq[3][0] = fma2(qb.y, sx[1], accq[3][0]);
                    accq[3][1] = fma2(qb.y, sx[2], accq[3][1]);
                }
            }
        }
        __syncthreads();
    }
    float* obv = outv + (size_t)b * NE * HW;
    float* obq = outq + (size_t)b * NE * HW;
    int rowoff = (yo + prow) * WW + xo + pcol0;
#pragma unroll
    for (int ep = 0; ep < 4; ep++) {
        int o0 = cg * 8 + ep * 2;
        float2 v0 = unpack2(accv[ep][0]), v1 = unpack2(accv[ep][1]);
        float bv0 = bias_v[o0], bv1 = bias_v[o0 + 1];
        *(float2*)&obv[(size_t)o0 * HW + rowoff] = make_float2(v0.x + bv0, v1.x + bv0);
        *(float2*)&obv[(size_t)(o0 + 1) * HW + rowoff] = make_float2(v0.y + bv1, v1.y + bv1);
        float2 q0 = unpack2(accq[ep][0]), q1 = unpack2(accq[ep][1]);
        float bq0 = bias_q[o0], bq1 = bias_q[o0 + 1];
        *(float2*)&obq[(size_t)o0 * HW + rowoff] = make_float2(q0.x + bq0, q1.x + bq0);
        *(float2*)&obq[(size_t)(o0 + 1) * HW + rowoff] = make_float2(q0.y + bq1, q1.y + bq1);
    }
}

// ============================================================
// Fused attention + output projection.
// Score/attend: lane=(pixel j, e-quarter). GEMM: lane = o.
// ============================================================
__device__ __forceinline__ void final_accum(
    const float* __restrict__ cat, const float* __restrict__ wsl,
    int lane, int wr, float out0[8], float out1[8])
{
#pragma unroll
    for (int it = 0; it < 8; it++) {
        int i0 = it * 8;
        float w0[8], w1[8];
#pragma unroll
        for (int jj = 0; jj < 8; jj++) {
            w0[jj] = wsl[(i0 + jj) * 65 + lane];
            w1[jj] = wsl[(i0 + jj) * 65 + 32 + lane];
        }
#pragma unroll
        for (int j = 0; j < 8; j++) {
            const float* cp = &cat[(wr * 8 + j) * 68 + i0];
            float4 ca = *(const float4*)cp;
            float4 cb = *(const float4*)(cp + 4);
            float s0 = out0[j];
            s0 = fmaf(w0[0], ca.x, s0); s0 = fmaf(w0[1], ca.y, s0);
            s0 = fmaf(w0[2], ca.z, s0); s0 = fmaf(w0[3], ca.w, s0);
            s0 = fmaf(w0[4], cb.x, s0); s0 = fmaf(w0[5], cb.y, s0);
            s0 = fmaf(w0[6], cb.z, s0); s0 = fmaf(w0[7], cb.w, s0);
            out0[j] = s0;
            float s1 = out1[j];
            s1 = fmaf(w1[0], ca.x, s1); s1 = fmaf(w1[1], ca.y, s1);
            s1 = fmaf(w1[2], ca.z, s1); s1 = fmaf(w1[3], ca.w, s1);
            s1 = fmaf(w1[4], cb.x, s1); s1 = fmaf(w1[5], cb.y, s1);
            s1 = fmaf(w1[6], cb.z, s1); s1 = fmaf(w1[7], cb.w, s1);
            out1[j] = s1;
        }
    }
}

__global__ void __launch_bounds__(256, 2) attn_kernel(
    const float* __restrict__ contexts,
    const float* __restrict__ w_agg,
    const float* __restrict__ b_agg_p,
    const float* __restrict__ b_attn,
    float* __restrict__ out)
{
    extern __shared__ __align__(16) float sm[];
    float* qs  = sm;                  // [64 pix][68]
    float* ks  = qs + 64 * 68;        // [100 halo][68]
    float* cs  = ks + 100 * 68;       // [100 halo][68]
    float* cat = cs + 100 * 68;       // [64 pix][68]
    float* wsl = cat + 64 * 68;       // [64 i][65]

    int tid = threadIdx.x, lane = tid & 31, wr = tid >> 5;
    int b = blockIdx.z, yo = blockIdx.y * 8, xo = blockIdx.x * 8;
    int j = lane >> 2, eq = lane & 3;
    int pix = wr * 8 + j;
    float bagg = b_agg_p[0];

    for (int lin = tid; lin < 4096; lin += 256) {
        int col = lin & 7, row = (lin >> 3) & 7, e = lin >> 6;
        int g = (b * NE + e) * HW + (yo + row) * WW + xo + col;
        qs[(row * 8 + col) * 68 + e] = g_queries[g];
        cat[(row * 8 + col) * 68 + e] = g_values[g];
    }
    for (int lin = tid; lin < 4096; lin += 256) {
        int o = lin & 63, i = lin >> 6;
        wsl[i * 65 + o] = g_wattnT[i * 64 + o];
    }
    __syncthreads();

    float qreg[16], waggr[16];
#pragma unroll
    for (int u = 0; u < 4; u++) {
        float4 qv = *(const float4*)&qs[pix * 68 + eq * 16 + u * 4];
        qreg[u*4] = qv.x; qreg[u*4+1] = qv.y; qreg[u*4+2] = qv.z; qreg[u*4+3] = qv.w;
        float4 wv = *(const float4*)&w_agg[eq * 16 + u * 4];
        waggr[u*4] = wv.x; waggr[u*4+1] = wv.y; waggr[u*4+2] = wv.z; waggr[u*4+3] = wv.w;
    }

    float out0[8], out1[8];
#pragma unroll
    for (int t = 0; t < 8; t++) { out0[t] = 0.f; out1[t] = 0.f; }
    final_accum(cat, wsl, lane, wr, out0, out1);

    for (int k = 0; k < NK; k++) {
        __syncthreads();
        const float* kb = g_keys + (size_t)(k * NB + b) * NE * HW;
        const float* cb = contexts + (size_t)(k * NB + b) * NE * HW;
        for (int lin = tid; lin < 6400; lin += 256) {
            int hc = lin % 10; int t = lin / 10; int hr = t % 10; int e = t / 10;
            int gy = yo - 1 + hr, gx = xo - 1 + hc;
            float kv = 0.f, cv = 0.f;
            if ((unsigned)gy < HH && (unsigned)gx < WW) {
                int g = e * HW + gy * WW + gx;
                kv = kb[g]; cv = cb[g];
            }
            ks[(hr * 10 + hc) * 68 + e] = kv;
            cs[(hr * 10 + hc) * 68 + e] = cv;
        }
        for (int lin = tid; lin < 4096; lin += 256) {
            int o = lin & 63, i = lin >> 6;
            wsl[i * 65 + o] = g_wattnT[((k + 1) * 64 + i) * 64 + o];
        }
        __syncthreads();

        int base_hp = wr * 10 + j;
        float s[9];
#pragma unroll
        for (int n = 0; n < 9; n++) {
            const int dr = n / 3, dc = n % 3;
            const float* kp = &ks[(base_hp + dr * 10 + dc) * 68 + eq * 16];
            float pa = 0.f, pb = 0.f;
#pragma unroll
            for (int u = 0; u < 2; u++) {
                float4 k0 = *(const float4*)(kp + u * 8);
                float4 k1 = *(const float4*)(kp + u * 8 + 4);
                pa = fmaf(waggr[u*8+0], tanh_fast(qreg[u*8+0] + k0.x), pa);
                pb = fmaf(waggr[u*8+1], tanh_fast(qreg[u*8+1] + k0.y), pb);
                pa = fmaf(waggr[u*8+2], tanh_fast(qreg[u*8+2] + k0.z), pa);
                pb = fmaf(waggr[u*8+3], tanh_fast(qreg[u*8+3] + k0.w), pb);
                pa = fmaf(waggr[u*8+4], tanh_fast(qreg[u*8+4] + k1.x), pa);
                pb = fmaf(waggr[u*8+5], tanh_fast(qreg[u*8+5] + k1.y), pb);
                pa = fmaf(waggr[u*8+6], tanh_fast(qreg[u*8+6] + k1.z), pa);
                pb = fmaf(waggr[u*8+7], tanh_fast(qreg[u*8+7] + k1.w), pb);
            }
            float part = pa + pb;
            part += __shfl_xor_sync(0xffffffffu, part, 1);
            part += __shfl_xor_sync(0xffffffffu, part, 2);
            bool valid = ((unsigned)(yo + wr + dr - 1) < HH) &&
                         ((unsigned)(xo + j + dc - 1) < WW);
            s[n] = valid ? part + bagg : -1e30f;
        }
        float m = s[0];
#pragma unroll
        for (int n = 1; n < 9; n++) m = fmaxf(m, s[n]);
        float p[9], ps = 0.f;
#pragma unroll
        for (int n = 0; n < 9; n++) { p[n] = __expf(s[n] - m); ps += p[n]; }
        float rinv = __fdividef(1.f, ps);

        ull a2[8];
#pragma unroll
        for (int t = 0; t < 8; t++) a2[t] = 0ull;
#pragma unroll
        for (int n = 0; n < 9; n++) {
            const int dr = n / 3, dc = n % 3;
            float pn = p[n] * rinv;
            ull pr = pack2(pn, pn);
            const float* cp = &cs[(base_hp + dr * 10 + dc) * 68 + eq * 16];
            ulonglong2 cA = *(const ulonglong2*)cp;
            ulonglong2 cB = *(const ulonglong2*)(cp + 4);
            ulonglong2 cC = *(const ulonglong2*)(cp + 8);
            ulonglong2 cD = *(const ulonglong2*)(cp + 12);
            a2[0] = fma2(pr, cA.x, a2[0]); a2[1] = fma2(pr, cA.y, a2[1]);
            a2[2] = fma2(pr, cB.x, a2[2]); a2[3] = fma2(pr, cB.y, a2[3]);
            a2[4] = fma2(pr, cC.x, a2[4]); a2[5] = fma2(pr, cC.y, a2[5]);
            a2[6] = fma2(pr, cD.x, a2[6]); a2[7] = fma2(pr, cD.y, a2[7]);
        }
        {
            float* dp = &cat[pix * 68 + eq * 16];
            ulonglong2 t0; t0.x = a2[0]; t0.y = a2[1]; *(ulonglong2*)dp = t0;
            ulonglong2 t1; t1.x = a2[2]; t1.y = a2[3]; *(ulonglong2*)(dp + 4) = t1;
            ulonglong2 t2; t2.x = a2[4]; t2.y = a2[5]; *(ulonglong2*)(dp + 8) = t2;
            ulonglong2 t3; t3.x = a2[6]; t3.y = a2[7]; *(ulonglong2*)(dp + 12) = t3;
        }
        __syncwarp();
        final_accum(cat, wsl, lane, wr, out0, out1);
    }

    float ba0 = b_attn[lane], ba1 = b_attn[lane + 32];
    __syncthreads();
#pragma unroll
    for (int t = 0; t < 8; t++) {
        int px = wr * 8 + t;
        float r0 = out0[t] + ba0; r0 = (r0 >= 0.f) ? r0 : 0.2f * r0;
        float r1 = out1[t] + ba1; r1 = (r1 >= 0.f) ? r1 : 0.2f * r1;
        cat[px * 68 + lane] = r0;
        cat[px * 68 + 32 + lane] = r1;
    }
    __syncthreads();
    for (int lin = tid; lin < 4096; lin += 256) {
        int col = lin & 7, row = (lin >> 3) & 7, e = lin >> 6;
        out[(b * NE + e) * HW + (yo + row) * WW + xo + col] =
            cat[(row * 8 + col) * 68 + e];
    }
}

// ============================================================
extern "C" void kernel_launch(void* const* d_in, const int* in_sizes, int n_in,
                              void* d_out, int out_size)
{
    (void)in_sizes; (void)n_in; (void)out_size;
    const float* contexts = (const float*)d_in[0];
    const float* decoded  = (const float*)d_in[1];
    const float* w_enc    = (const float*)d_in[2];
    const float* b_enc    = (const float*)d_in[3];
    const float* w_dec    = (const float*)d_in[4];
    const float* b_dec    = (const float*)d_in[5];
    const float* w_agg    = (const float*)d_in[6];
    const float* b_agg    = (const float*)d_in[7];
    const float* w_val    = (const float*)d_in[8];
    const float* b_val    = (const float*)d_in[9];
    const float* w_attn   = (const float*)d_in[10];
    const float* b_attn   = (const float*)d_in[11];
    float* out = (float*)d_out;

    float *gq, *gk, *gv;
    cudaGetSymbolAddress((void**)&gq, g_queries);
    cudaGetSymbolAddress((void**)&gk, g_keys);
    cudaGetSymbolAddress((void**)&gv, g_values);

    repack_kernel<<<416, 256>>>(w_val, w_dec, w_enc, w_attn);
    keys_kernel<<<dim3(72, NK * NB), 256>>>(contexts, b_enc, gk);
    conv3x3q_kernel<<<dim3(12, 12, NB), 256>>>(decoded, b_val, b_dec, gv, gq);

    const int SMEM_ATTN = (64 * 68 + 100 * 68 + 100 * 68 + 64 * 68 + 64 * 65) * 4;
    cudaFuncSetAttribute(attn_kernel,
                         cudaFuncAttributeMaxDynamicSharedMemorySize, SMEM_ATTN);
    attn_kernel<<<dim3(12, 12, NB), 256, SMEM_ATTN>>>(
        contexts, w_agg, b_agg, b_attn, out);
}

// round 4
// speedup vs baseline: 1.6279x; 1.0616x over previous
#include <cuda_runtime.h>

#define HH 96
#define WW 96
#define HW 9216
#define NE 64
#define ND 128
#define NK 4
#define NB 2

typedef unsigned long long ull;

// scratch — all pixel-major [img][pix][e] layouts
__device__ float g_queries[NB * HW * NE];
__device__ float g_keys[NK * NB * HW * NE];
__device__ float g_values[NB * HW * NE];
__device__ float g_ctxT[NK * NB * HW * NE];
__device__ float g_wpack[ND * 9 * NE];        // [ci][tap][o]
__device__ float g_wdecT[ND * NE];            // [ci][o]
__device__ float g_wencT[NE * NE];            // [ci][o]
__device__ float g_wattnT2[5 * 32 * NE * 2];  // [phase][ipair][o][2] = (w[2i][o], w[2i+1][o])

__device__ __forceinline__ ull fma2(ull a, ull b, ull c) {
    ull d;
    asm("fma.rn.f32x2 %0, %1, %2, %3;" : "=l"(d) : "l"(a), "l"(b), "l"(c));
    return d;
}
__device__ __forceinline__ ull pack2(float x, float y) {
    ull r; asm("mov.b64 %0, {%1, %2};" : "=l"(r) : "f"(x), "f"(y)); return r;
}
__device__ __forceinline__ float2 unpack2(ull v) {
    float lo, hi; asm("mov.b64 {%0, %1}, %2;" : "=f"(lo), "=f"(hi) : "l"(v));
    return make_float2(lo, hi);
}
__device__ __forceinline__ float tanh_fast(float x) {
    float y; asm("tanh.approx.f32 %0, %1;" : "=f"(y) : "f"(x)); return y;
}

// ============================================================
__global__ void __launch_bounds__(256) repack_kernel(
    const float* __restrict__ wv, const float* __restrict__ wd,
    const float* __restrict__ we, const float* __restrict__ wa)
{
    int i = blockIdx.x * 256 + threadIdx.x;
    if (i < 73728) {
        int o = i & 63; int t = i >> 6; int tap = t % 9; int ci = t / 9;
        g_wpack[i] = wv[(size_t)o * (ND * 9) + ci * 9 + tap];
    } else if (i < 81920) {
        int r = i - 73728; int o = r & 63; int ci = r >> 6;
        g_wdecT[r] = wd[o * ND + ci];
    } else if (i < 86016) {
        int r = i - 81920; int o = r & 63; int ci = r >> 6;
        g_wencT[r] = we[o * NE + ci];
    } else if (i < 106496) {
        int r = i - 86016;           // [phase][ip][o][half]
        int half = r & 1; int r2 = r >> 1;
        int o = r2 & 63; int t = r2 >> 6; int ip = t & 31; int k = t >> 5;
        g_wattnT2[r] = wa[o * 320 + k * 64 + 2 * ip + half];
    }
}

// ============================================================
// keys 1x1 conv (f32x2 over e-pairs) + context transpose.
// Writes keys AND ctx in [img][pix][e] layout.
// ============================================================
__global__ void __launch_bounds__(256) keys_kernel(
    const float* __restrict__ x, const float* __restrict__ bias,
    float* __restrict__ out, float* __restrict__ outc)
{
    __shared__ __align__(16) float xs[16][128];
    __shared__ __align__(16) float ws[16 * 64];
    int tid = threadIdx.x, lane = tid & 31, cg = tid >> 5;
    int img = blockIdx.y;
    int p0 = blockIdx.x * 128;
    const float* xb = x + (size_t)img * NE * HW + p0;

    ull acc2[4][4];
#pragma unroll
    for (int ep = 0; ep < 4; ep++)
#pragma unroll
        for (int px = 0; px < 4; px++) acc2[ep][px] = 0ull;

    int tpx = tid >> 1, thalf = tid & 1;

    for (int c0 = 0; c0 < NE; c0 += 16) {
#pragma unroll
        for (int rep = 0; rep < 2; rep++) {
            int lin = tid + rep * 256;
            int ci = lin >> 5, px4 = (lin & 31) * 4;
            *(float4*)&xs[ci][px4] = *(const float4*)&xb[(size_t)(c0 + ci) * HW + px4];
        }
        ((float4*)ws)[tid] = ((const float4*)(g_wencT + c0 * 64))[tid];
        __syncthreads();
        // transpose ctx chunk to [pix][e]
        {
            float v[8];
#pragma unroll
            for (int t = 0; t < 8; t++) v[t] = xs[thalf * 8 + t][tpx];
            float* cd = &outc[((size_t)img * HW + p0 + tpx) * NE + c0 + thalf * 8];
            *(float4*)cd = make_float4(v[0], v[1], v[2], v[3]);
            *(float4*)(cd + 4) = make_float4(v[4], v[5], v[6], v[7]);
        }
#pragma unroll
        for (int ci = 0; ci < 16; ci++) {
            float4 xv = *(float4*)&xs[ci][lane * 4];
            ull sx[4] = {pack2(xv.x, xv.x), pack2(xv.y, xv.y),
                         pack2(xv.z, xv.z), pack2(xv.w, xv.w)};
            ulonglong2 wa = *(const ulonglong2*)&ws[ci * 64 + cg * 8];
            ulonglong2 wb = *(const ulonglong2*)&ws[ci * 64 + cg * 8 + 4];
#pragma unroll
            for (int px = 0; px < 4; px++) {
                acc2[0][px] = fma2(wa.x, sx[px], acc2[0][px]);
                acc2[1][px] = fma2(wa.y, sx[px], acc2[1][px]);
                acc2[2][px] = fma2(wb.x, sx[px], acc2[2][px]);
                acc2[3][px] = fma2(wb.y, sx[px], acc2[3][px]);
            }
        }
        __syncthreads();
    }
    float4 ba = *(const float4*)&bias[cg * 8];
    float4 bb = *(const float4*)&bias[cg * 8 + 4];
#pragma unroll
    for (int px = 0; px < 4; px++) {
        float2 u0 = unpack2(acc2[0][px]), u1 = unpack2(acc2[1][px]);
        float2 u2 = unpack2(acc2[2][px]), u3 = unpack2(acc2[3][px]);
        float* dst = &out[((size_t)img * HW + p0 + lane * 4 + px) * NE + cg * 8];
        *(float4*)dst = make_float4(u0.x + ba.x, u0.y + ba.y, u1.x + ba.z, u1.y + ba.w);
        *(float4*)(dst + 4) = make_float4(u2.x + bb.x, u2.y + bb.y, u3.x + bb.z, u3.y + bb.w);
    }
}

// ============================================================
// 3x3 conv (values) + fused queries 1x1, f32x2 over e-pairs.
// Outputs in [img][pix][e] layout.
// ============================================================
__global__ void __launch_bounds__(256, 2) conv3x3q_kernel(
    const float* __restrict__ x, const float* __restrict__ bias_v,
    const float* __restrict__ bias_q,
    float* __restrict__ outv, float* __restrict__ outq)
{
    __shared__ __align__(16) float xs[16][112];
    __shared__ __align__(16) float ws[16 * 9 * 64];
    __shared__ __align__(16) float wq[16 * 64];
    int tid = threadIdx.x, lane = tid & 31, cg = tid >> 5;
    int b = blockIdx.z;
    int yo = blockIdx.y * 8, xo = blockIdx.x * 8;
    int prow = lane >> 2, pcol0 = (lane & 3) * 2;
    const float* xb = x + (size_t)b * ND * HW;

    ull accv[4][2], accq[4][2];
#pragma unroll
    for (int ep = 0; ep < 4; ep++) {
        accv[ep][0] = accv[ep][1] = 0ull;
        accq[ep][0] = accq[ep][1] = 0ull;
    }

    for (int c0 = 0; c0 < ND; c0 += 16) {
        for (int lin = tid; lin < 1600; lin += 256) {
            int hc = lin % 10; int t = lin / 10; int hr = t % 10; int ci = t / 10;
            int gy = yo - 1 + hr, gx = xo - 1 + hc;
            float v = 0.f;
            if ((unsigned)gy < HH && (unsigned)gx < WW)
                v = xb[(size_t)(c0 + ci) * HW + gy * WW + gx];
            xs[ci][hr * 11 + hc] = v;
        }
#pragma unroll
        for (int r = 0; r < 9; r++)
            ((float4*)ws)[tid + r * 256] =
                ((const float4*)(g_wpack + c0 * 576))[tid + r * 256];
        ((float4*)wq)[tid] = ((const float4*)(g_wdecT + c0 * 64))[tid];
        __syncthreads();
#pragma unroll
        for (int ci = 0; ci < 16; ci++) {
#pragma unroll
            for (int dr = 0; dr < 3; dr++) {
                int rb = (prow + dr) * 11 + pcol0;
                float x0 = xs[ci][rb], x1 = xs[ci][rb + 1];
                float x2 = xs[ci][rb + 2], x3 = xs[ci][rb + 3];
                ull sx[4] = {pack2(x0, x0), pack2(x1, x1),
                             pack2(x2, x2), pack2(x3, x3)};
#pragma unroll
                for (int dc = 0; dc < 3; dc++) {
                    const float* wp = ws + (ci * 9 + dr * 3 + dc) * 64 + cg * 8;
                    ulonglong2 wa = *(const ulonglong2*)wp;
                    ulonglong2 wb = *(const ulonglong2*)(wp + 4);
                    accv[0][0] = fma2(wa.x, sx[dc], accv[0][0]);
                    accv[0][1] = fma2(wa.x, sx[dc + 1], accv[0][1]);
                    accv[1][0] = fma2(wa.y, sx[dc], accv[1][0]);
                    accv[1][1] = fma2(wa.y, sx[dc + 1], accv[1][1]);
                    accv[2][0] = fma2(wb.x, sx[dc], accv[2][0]);
                    accv[2][1] = fma2(wb.x, sx[dc + 1], accv[2][1]);
                    accv[3][0] = fma2(wb.y, sx[dc], accv[3][0]);
                    accv[3][1] = fma2(wb.y, sx[dc + 1], accv[3][1]);
                }
                if (dr == 1) {
                    const float* qp = wq + ci * 64 + cg * 8;
                    ulonglong2 qa = *(const ulonglong2*)qp;
                    ulonglong2 qb = *(const ulonglong2*)(qp + 4);
                    accq[0][0] = fma2(qa.x, sx[1], accq[0][0]);
                    accq[0][1] = fma2(qa.x, sx[2], accq[0][1]);
                    accq[1][0] = fma2(qa.y, sx[1], accq[1][0]);
                    accq[1][1] = fma2(qa.y, sx[2], accq[1][1]);
                    accq[2][0] = fma2(qb.x, sx[1], accq[2][0]);
                    accq[2][1] = fma2(qb.x, sx[2], accq[2][1]);
                    accq[3][0] = fma2(qb.y, sx[1], accq[3][0]);
                    accq[3][1] = fma2(qb.y, sx[2], accq[3][1]);
                }
            }
        }
        __syncthreads();
    }
    float4 bva = *(const float4*)&bias_v[cg * 8];
    float4 bvb = *(const float4*)&bias_v[cg * 8 + 4];
    float4 bqa = *(const float4*)&bias_q[cg * 8];
    float4 bqb = *(const float4*)&bias_q[cg * 8 + 4];
    int gp0 = (yo + prow) * WW + xo + pcol0;
#pragma unroll
    for (int pxi = 0; pxi < 2; pxi++) {
        float2 u0 = unpack2(accv[0][pxi]), u1 = unpack2(accv[1][pxi]);
        float2 u2 = unpack2(accv[2][pxi]), u3 = unpack2(accv[3][pxi]);
        float* dv = &outv[((size_t)b * HW + gp0 + pxi) * NE + cg * 8];
        *(float4*)dv = make_float4(u0.x + bva.x, u0.y + bva.y, u1.x + bva.z, u1.y + bva.w);
        *(float4*)(dv + 4) = make_float4(u2.x + bvb.x, u2.y + bvb.y, u3.x + bvb.z, u3.y + bvb.w);
        float2 q0 = unpack2(accq[0][pxi]), q1 = unpack2(accq[1][pxi]);
        float2 q2 = unpack2(accq[2][pxi]), q3 = unpack2(accq[3][pxi]);
        float* dq = &outq[((size_t)b * HW + gp0 + pxi) * NE + cg * 8];
        *(float4*)dq = make_float4(q0.x + bqa.x, q0.y + bqa.y, q1.x + bqa.z, q1.y + bqa.w);
        *(float4*)(dq + 4) = make_float4(q2.x + bqb.x, q2.y + bqb.y, q3.x + bqb.z, q3.y + bqb.w);
    }
}

// ============================================================
// Fused attention + output projection.
// ============================================================
__device__ __forceinline__ void final_accum(
    const float* __restrict__ cat, const ull* __restrict__ wsl2,
    int lane, int wr, ull acc0[8], ull acc1[8])
{
#pragma unroll
    for (int it = 0; it < 8; it++) {
        ull w0[4], w1[4];
#pragma unroll
        for (int t = 0; t < 4; t++) {
            int ip = it * 4 + t;
            w0[t] = wsl2[ip * 66 + lane];
            w1[t] = wsl2[ip * 66 + 32 + lane];
        }
#pragma unroll
        for (int j = 0; j < 8; j++) {
            const ull* cp = (const ull*)&cat[(wr * 8 + j) * 68 + it * 8];
            ulonglong2 cA = *(const ulonglong2*)cp;
            ulonglong2 cB = *(const ulonglong2*)(cp + 2);
            ull a0 = acc0[j];
            a0 = fma2(w0[0], cA.x, a0); a0 = fma2(w0[1], cA.y, a0);
            a0 = fma2(w0[2], cB.x, a0); a0 = fma2(w0[3], cB.y, a0);
            acc0[j] = a0;
            ull a1 = acc1[j];
            a1 = fma2(w1[0], cA.x, a1); a1 = fma2(w1[1], cA.y, a1);
            a1 = fma2(w1[2], cB.x, a1); a1 = fma2(w1[3], cB.y, a1);
            acc1[j] = a1;
        }
    }
}

__global__ void __launch_bounds__(256, 2) attn_kernel(
    const float* __restrict__ w_agg,
    const float* __restrict__ b_agg_p,
    const float* __restrict__ b_attn,
    float* __restrict__ out)
{
    extern __shared__ __align__(16) float sm[];
    float* ks  = sm;                   // [100 halo][68]
    float* cs  = ks + 100 * 68;        // [100 halo][68]
    float* cat = cs + 100 * 68;        // [64 pix][68]
    ull* wsl2  = (ull*)(cat + 64 * 68); // [32 ipair][66]

    int tid = threadIdx.x, lane = tid & 31, wr = tid >> 5;
    int b = blockIdx.z, yo = blockIdx.y * 8, xo = blockIdx.x * 8;
    int j = lane >> 2, eq = lane & 3;
    int pix = wr * 8 + j;
    float bagg = b_agg_p[0];

    // load values tile -> cat, and w_attn phase 0 -> wsl2
    {
        const float* vb = g_values + (size_t)b * HW * NE;
        for (int lin = tid; lin < 1024; lin += 256) {
            int p = lin >> 4, e4 = (lin & 15) * 4;
            int gp = (yo + (p >> 3)) * WW + xo + (p & 7);
            *(float4*)&cat[p * 68 + e4] = *(const float4*)&vb[(size_t)gp * NE + e4];
        }
        const ulonglong2* wsrc = (const ulonglong2*)g_wattnT2;
        for (int lin = tid; lin < 1024; lin += 256) {
            ulonglong2 u = wsrc[lin];
            int o2 = (lin & 31) * 2, ip = lin >> 5;
            *(ulonglong2*)&wsl2[ip * 66 + o2] = u;
        }
    }

    // queries + w_agg direct to registers
    float qreg[16], waggr[16];
    {
        const float* qb = g_queries +
            ((size_t)b * HW + (yo + wr) * WW + xo + j) * NE + eq * 16;
#pragma unroll
        for (int u = 0; u < 4; u++) {
            float4 qv = *(const float4*)(qb + u * 4);
            qreg[u*4] = qv.x; qreg[u*4+1] = qv.y; qreg[u*4+2] = qv.z; qreg[u*4+3] = qv.w;
            float4 wv = *(const float4*)&w_agg[eq * 16 + u * 4];
            waggr[u*4] = wv.x; waggr[u*4+1] = wv.y; waggr[u*4+2] = wv.z; waggr[u*4+3] = wv.w;
        }
    }
    __syncthreads();

    ull acc0[8], acc1[8];
#pragma unroll
    for (int t = 0; t < 8; t++) { acc0[t] = 0ull; acc1[t] = 0ull; }
    final_accum(cat, wsl2, lane, wr, acc0, acc1);

    for (int k = 0; k < NK; k++) {
        __syncthreads();
        const float* kb = g_keys + (size_t)(k * NB + b) * HW * NE;
        const float* cb = g_ctxT + (size_t)(k * NB + b) * HW * NE;
        for (int lin = tid; lin < 1600; lin += 256) {
            int hp = lin >> 4, e4 = (lin & 15) * 4;
            int hr = hp / 10, hc = hp % 10;
            int gy = yo - 1 + hr, gx = xo - 1 + hc;
            float4 kv = make_float4(0.f, 0.f, 0.f, 0.f), cv = kv;
            if ((unsigned)gy < HH && (unsigned)gx < WW) {
                size_t off = ((size_t)gy * WW + gx) * NE + e4;
                kv = *(const float4*)&kb[off];
                cv = *(const float4*)&cb[off];
            }
            *(float4*)&ks[hp * 68 + e4] = kv;
            *(float4*)&cs[hp * 68 + e4] = cv;
        }
        const ulonglong2* wsrc = (const ulonglong2*)g_wattnT2 + (k + 1) * 1024;
        for (int lin = tid; lin < 1024; lin += 256) {
            ulonglong2 u = wsrc[lin];
            int o2 = (lin & 31) * 2, ip = lin >> 5;
            *(ulonglong2*)&wsl2[ip * 66 + o2] = u;
        }
        __syncthreads();

        int base_hp = wr * 10 + j;
        float s[9];
#pragma unroll
        for (int n = 0; n < 9; n++) {
            const int dr = n / 3, dc = n % 3;
            const float* kp = &ks[(base_hp + dr * 10 + dc) * 68 + eq * 16];
            float pa = 0.f, pb = 0.f;
#pragma unroll
            for (int u = 0; u < 2; u++) {
                float4 k0 = *(const float4*)(kp + u * 8);
                float4 k1 = *(const float4*)(kp + u * 8 + 4);
                pa = fmaf(waggr[u*8+0], tanh_fast(qreg[u*8+0] + k0.x), pa);
                pb = fmaf(waggr[u*8+1], tanh_fast(qreg[u*8+1] + k0.y), pb);
                pa = fmaf(waggr[u*8+2], tanh_fast(qreg[u*8+2] + k0.z), pa);
                pb = fmaf(waggr[u*8+3], tanh_fast(qreg[u*8+3] + k0.w), pb);
                pa = fmaf(waggr[u*8+4], tanh_fast(qreg[u*8+4] + k1.x), pa);
                pb = fmaf(waggr[u*8+5], tanh_fast(qreg[u*8+5] + k1.y), pb);
                pa = fmaf(waggr[u*8+6], tanh_fast(qreg[u*8+6] + k1.z), pa);
                pb = fmaf(waggr[u*8+7], tanh_fast(qreg[u*8+7] + k1.w), pb);
            }
            float part = pa + pb;
            part += __shfl_xor_sync(0xffffffffu, part, 1);
            part += __shfl_xor_sync(0xffffffffu, part, 2);
            bool valid = ((unsigned)(yo + wr + dr - 1) < HH) &&
                         ((unsigned)(xo + j + dc - 1) < WW);
            s[n] = valid ? part + bagg : -1e30f;
        }
        float m = s[0];
#pragma unroll
        for (int n = 1; n < 9; n++) m = fmaxf(m, s[n]);
        float p[9], ps = 0.f;
#pragma unroll
        for (int n = 0; n < 9; n++) { p[n] = __expf(s[n] - m); ps += p[n]; }
        float rinv = __fdividef(1.f, ps);

        ull a2[8];
#pragma unroll
        for (int t = 0; t < 8; t++) a2[t] = 0ull;
#pragma unroll
        for (int n = 0; n < 9; n++) {
            const int dr = n / 3, dc = n % 3;
            float pn = p[n] * rinv;
            ull pr = pack2(pn, pn);
            const float* cp = &cs[(base_hp + dr * 10 + dc) * 68 + eq * 16];
            ulonglong2 cA = *(const ulonglong2*)cp;
            ulonglong2 cB = *(const ulonglong2*)(cp + 4);
            ulonglong2 cC = *(const ulonglong2*)(cp + 8);
            ulonglong2 cD = *(const ulonglong2*)(cp + 12);
            a2[0] = fma2(pr, cA.x, a2[0]); a2[1] = fma2(pr, cA.y, a2[1]);
            a2[2] = fma2(pr, cB.x, a2[2]); a2[3] = fma2(pr, cB.y, a2[3]);
            a2[4] = fma2(pr, cC.x, a2[4]); a2[5] = fma2(pr, cC.y, a2[5]);
            a2[6] = fma2(pr, cD.x, a2[6]); a2[7] = fma2(pr, cD.y, a2[7]);
        }
        {
            float* dp = &cat[pix * 68 + eq * 16];
            ulonglong2 t0; t0.x = a2[0]; t0.y = a2[1]; *(ulonglong2*)dp = t0;
            ulonglong2 t1; t1.x = a2[2]; t1.y = a2[3]; *(ulonglong2*)(dp + 4) = t1;
            ulonglong2 t2; t2.x = a2[4]; t2.y = a2[5]; *(ulonglong2*)(dp + 8) = t2;
            ulonglong2 t3; t3.x = a2[6]; t3.y = a2[7]; *(ulonglong2*)(dp + 12) = t3;
        }
        __syncwarp();
        final_accum(cat, wsl2, lane, wr, acc0, acc1);
    }

    // epilogue: horizontal add, bias + LeakyReLU, transpose via smem
    float ba0 = b_attn[lane], ba1 = b_attn[lane + 32];
    __syncthreads();
#pragma unroll
    for (int t = 0; t < 8; t++) {
        int px = wr * 8 + t;
        float2 z0 = unpack2(acc0[t]);
        float2 z1 = unpack2(acc1[t]);
        float r0 = z0.x + z0.y + ba0; r0 = (r0 >= 0.f) ? r0 : 0.2f * r0;
        float r1 = z1.x + z1.y + ba1; r1 = (r1 >= 0.f) ? r1 : 0.2f * r1;
        cat[px * 68 + lane] = r0;
        cat[px * 68 + 32 + lane] = r1;
    }
    __syncthreads();
    for (int lin = tid; lin < 4096; lin += 256) {
        int col = lin & 7, row = (lin >> 3) & 7, e = lin >> 6;
        out[(b * NE + e) * HW + (yo + row) * WW + xo + col] =
            cat[(row * 8 + col) * 68 + e];
    }
}

// ============================================================
extern "C" void kernel_launch(void* const* d_in, const int* in_sizes, int n_in,
                              void* d_out, int out_size)
{
    (void)in_sizes; (void)n_in; (void)out_size;
    const float* contexts = (const float*)d_in[0];
    const float* decoded  = (const float*)d_in[1];
    const float* w_enc    = (const float*)d_in[2];
    const float* b_enc    = (const float*)d_in[3];
    const float* w_dec    = (const float*)d_in[4];
    const float* b_dec    = (const float*)d_in[5];
    const float* w_agg    = (const float*)d_in[6];
    const float* b_agg    = (const float*)d_in[7];
    const float* w_val    = (const float*)d_in[8];
    const float* b_val    = (const float*)d_in[9];
    const float* w_attn   = (const float*)d_in[10];
    const float* b_attn   = (const float*)d_in[11];
    float* out = (float*)d_out;

    float *gq, *gk, *gv, *gc;
    cudaGetSymbolAddress((void**)&gq, g_queries);
    cudaGetSymbolAddress((void**)&gk, g_keys);
    cudaGetSymbolAddress((void**)&gv, g_values);
    cudaGetSymbolAddress((void**)&gc, g_ctxT);

    repack_kernel<<<416, 256>>>(w_val, w_dec, w_enc, w_attn);
    keys_kernel<<<dim3(72, NK * NB), 256>>>(contexts, b_enc, gk, gc);
    conv3x3q_kernel<<<dim3(12, 12, NB), 256>>>(decoded, b_val, b_dec, gv, gq);

    const int SMEM_ATTN = (100 * 68 + 100 * 68 + 64 * 68 + 32 * 66 * 2) * 4;
    cudaFuncSetAttribute(attn_kernel,
                         cudaFuncAttributeMaxDynamicSharedMemorySize, SMEM_ATTN);
    attn_kernel<<<dim3(12, 12, NB), 256, SMEM_ATTN>>>(
        w_agg, b_agg, b_attn, out);
}